// round 15
// baseline (speedup 1.0000x reference)
#include <cuda_runtime.h>
#include <cstdint>

// Problem constants (fixed shapes per reference setup_inputs)
#define S 8192      // tokens
#define M 2048      // model dim
#define E 64        // experts
#define CAP 256     // capacity = TOP_K * ceil(S/E) = 2 * 128
#define KSPLIT 4
#define KCHUNK (M / KSPLIT)   // 512
#define BK 16
#define BM 128                // tokens per gemm block
#define NMB (S / BM)          // 64 token-blocks
#define NG (NMB * KSPLIT)     // 256 gemm blocks
#define NT (KCHUNK / BK)      // 32 k-tiles
#define CHUNK_F4 8192         // 128 KB zero-fill chunk
#define P1_CHUNKS 2048        // 256 MB zeroed inside K1 (mixed phase)
#define K1_GRID 444           // 148 SMs * 3 blocks -> single wave
#define NF2B 1184             // 148 SMs * 8 blocks -> K2 persistent fill

typedef unsigned long long ull;

// ---- device scratch (no allocations allowed) ----
__device__ float g_part[KSPLIT][S][E];  // 8 MB partial logits (L2-resident)
__device__ int   g_expert[S];
__device__ float g_gate[S];
__device__ int   g_cnt_mb[NMB];         // per token-group gemm completion
__device__ int   g_pool1;               // K1 fill chunk pool
__device__ int   g_pool2;               // K2 fill chunk pool
__device__ int   g_k2_done;             // K2 fill blocks finished

__device__ __forceinline__ ull dup2(float x) {
    ull r; asm("mov.b64 %0, {%1, %1};" : "=l"(r) : "f"(x)); return r;
}
__device__ __forceinline__ void ffma2(ull &acc, ull a, ull b) {
    asm("fma.rn.f32x2 %0, %1, %2, %0;" : "+l"(acc) : "l"(a), "l"(b));
}
__device__ __forceinline__ float2 unpack2(ull v) {
    float2 f; asm("mov.b64 {%0, %1}, %2;" : "=f"(f.x), "=f"(f.y) : "l"(v));
    return f;
}

__global__ void init_kernel() {
    if (threadIdx.x < NMB) g_cnt_mb[threadIdx.x] = 0;
    if (threadIdx.x == 0) { g_pool1 = 0; g_pool2 = 0; g_k2_done = 0; }
}

// ============================================================
// K1: 256 GEMM blocks + 188 fill blocks, single wave (3/SM).
// Everyone drains the P1 chunk pool; per-mb last finisher runs
// softargmax for its 128 tokens. Kernel ends ~ when GEMM ends.
// ============================================================
__global__ void __launch_bounds__(256, 3) k1_kernel(const float* __restrict__ A,
                                                    const float* __restrict__ B,
                                                    float4* __restrict__ out4,
                                                    int p1) {
    __shared__ __align__(16) float As[BK][BM];        // [k][token]
    __shared__ __align__(16) ull   Bs[2][BK][32];     // [plane][k][slot], dup'd {b,b}
    __shared__ int s_last;
    __shared__ int s_chunk;

    const int bx  = blockIdx.x;
    const int tid = threadIdx.x;
    const float4 z = make_float4(0.f, 0.f, 0.f, 0.f);

    if (bx < NG) {
        // ---------------- gemm (128x64 block tile, 8x4 thread tile) ----------------
        const int mb  = bx & (NMB - 1);
        const int ks  = bx >> 6;
        const int tokBase = mb * BM;
        const int kb0 = ks * KCHUNK;

        const int atok = tid & 127;
        const int akq  = tid >> 7;        // 0 or 1
        const float* arow = A + (size_t)(tokBase + atok) * M + kb0;

        const int be = tid >> 2;
        const int bj = tid & 3;
        const float* brow = B + (size_t)be * M + kb0 + bj * 4;
        const int bp   = (be >> 1) & 1;
        const int bslt = (be >> 2) * 2 + (be & 1);

        const int tt = tid >> 4;
        const int te = tid & 15;

        ull acc[4][4];
        #pragma unroll
        for (int p = 0; p < 4; p++)
            #pragma unroll
            for (int j = 0; j < 4; j++) acc[p][j] = 0ull;

        float4 a0 = *(const float4*)(arow + akq * 4);
        float4 a1 = *(const float4*)(arow + akq * 4 + 8);
        float4 bv = *(const float4*)(brow);

        for (int tile = 0; tile < NT; tile++) {
            __syncthreads();

            As[akq*4 + 0][atok] = a0.x;  As[akq*4 + 1][atok] = a0.y;
            As[akq*4 + 2][atok] = a0.z;  As[akq*4 + 3][atok] = a0.w;
            As[akq*4 + 8][atok] = a1.x;  As[akq*4 + 9][atok] = a1.y;
            As[akq*4 +10][atok] = a1.z;  As[akq*4 +11][atok] = a1.w;

            Bs[bp][bj*4 + 0][bslt] = dup2(bv.x);
            Bs[bp][bj*4 + 1][bslt] = dup2(bv.y);
            Bs[bp][bj*4 + 2][bslt] = dup2(bv.z);
            Bs[bp][bj*4 + 3][bslt] = dup2(bv.w);

            __syncthreads();

            if (tile + 1 < NT) {
                const int kb = (tile + 1) * BK;
                a0 = *(const float4*)(arow + kb + akq * 4);
                a1 = *(const float4*)(arow + kb + akq * 4 + 8);
                bv = *(const float4*)(brow + kb);
            }

            #pragma unroll
            for (int kk = 0; kk < BK; kk++) {
                const ulonglong2* ar = (const ulonglong2*)&As[kk][tt * 8];
                ulonglong2 a01 = ar[0];
                ulonglong2 a23 = ar[1];
                ulonglong2 b0 = ((const ulonglong2*)&Bs[0][kk][0])[te];
                ulonglong2 b1 = ((const ulonglong2*)&Bs[1][kk][0])[te];
                ull ap[4] = { a01.x, a01.y, a23.x, a23.y };
                #pragma unroll
                for (int p = 0; p < 4; p++) {
                    ffma2(acc[p][0], ap[p], b0.x);
                    ffma2(acc[p][1], ap[p], b0.y);
                    ffma2(acc[p][2], ap[p], b1.x);
                    ffma2(acc[p][3], ap[p], b1.y);
                }
            }
        }

        #pragma unroll
        for (int p = 0; p < 4; p++) {
            float2 v0 = unpack2(acc[p][0]);
            float2 v1 = unpack2(acc[p][1]);
            float2 v2 = unpack2(acc[p][2]);
            float2 v3 = unpack2(acc[p][3]);
            int r0 = tokBase + tt * 8 + 2 * p;
            *(float4*)&g_part[ks][r0    ][te * 4] = make_float4(v0.x, v1.x, v2.x, v3.x);
            *(float4*)&g_part[ks][r0 + 1][te * 4] = make_float4(v0.y, v1.y, v2.y, v3.y);
        }

        // release partials, detect last finisher of this token group
        __threadfence();
        __syncthreads();
        if (tid == 0) s_last = (atomicAdd(&g_cnt_mb[mb], 1) == KSPLIT - 1);
        __syncthreads();

        if (s_last) {
            __threadfence();  // acquire: peer partials visible
            const int warp = tid >> 5;
            const int lane = tid & 31;
            #pragma unroll 2
            for (int i = 0; i < 16; i++) {
                int t = tokBase + warp * 16 + i;
                float v0 = 0.f, v1 = 0.f;
                #pragma unroll
                for (int k = 0; k < KSPLIT; k++) {
                    v0 += __ldcg(&g_part[k][t][lane]);
                    v1 += __ldcg(&g_part[k][t][lane + 32]);
                }
                float bvv; int bi;
                if (v0 >= v1) { bvv = v0; bi = lane; }
                else          { bvv = v1; bi = lane + 32; }
                #pragma unroll
                for (int off = 16; off; off >>= 1) {
                    float ov = __shfl_xor_sync(0xffffffffu, bvv, off);
                    int   oi = __shfl_xor_sync(0xffffffffu, bi, off);
                    if (ov > bvv || (ov == bvv && oi < bi)) { bvv = ov; bi = oi; }
                }
                float ssum = expf(v0 - bvv) + expf(v1 - bvv);
                #pragma unroll
                for (int off = 16; off; off >>= 1)
                    ssum += __shfl_xor_sync(0xffffffffu, ssum, off);
                if (lane == 0) {
                    g_expert[t] = bi;
                    g_gate[t]   = 1.0f / ssum;
                }
            }
        }
        // fall through: join the fill pool
    }

    // ---------------- work-steal zero-fill (all K1 blocks) ----------------
    for (;;) {
        __syncthreads();
        if (tid == 0) s_chunk = atomicAdd(&g_pool1, 1);
        __syncthreads();
        int c = s_chunk;
        if (c >= p1) break;
        float4* p = out4 + (size_t)c * CHUNK_F4 + tid;
        #pragma unroll 8
        for (int i = 0; i < CHUNK_F4 / 256; i++) { __stcs(p, z); p += 256; }
    }
}

// ============================================================
// K2: 32-reg budget -> 8 blocks/SM -> 64 fill warps/SM.
//   [0, NF2B)      : persistent work-steal fill of the remainder
//   [NF2B, NF2B+E) : rank+scatter (spin on K2 fill completion;
//                    K1 state is ordered by the stream)
// ============================================================
__global__ void __launch_bounds__(256, 8) k2_kernel(float4* __restrict__ out4,
                                                    float* __restrict__ outF,
                                                    int p1, int p2, int two) {
    const int bx  = blockIdx.x;
    const int tid = threadIdx.x;

    if (bx < NF2B) {
        __shared__ int s_chunk;
        const float4 z = make_float4(0.f, 0.f, 0.f, 0.f);
        for (;;) {
            __syncthreads();
            if (tid == 0) s_chunk = atomicAdd(&g_pool2, 1);
            __syncthreads();
            int c = s_chunk;
            if (c >= p2) break;
            float4* p = out4 + (size_t)(p1 + c) * CHUNK_F4 + tid;
            #pragma unroll 8
            for (int i = 0; i < CHUNK_F4 / 256; i++) { __stcs(p, z); p += 256; }
        }
        __threadfence();
        __syncthreads();
        if (tid == 0) atomicAdd(&g_k2_done, 1);
        return;
    }

    // ---------------- rank + scatter ----------------
    const int e = bx - NF2B;
    if (tid == 0) {
        volatile int* d = &g_k2_done;
        while (*d < NF2B) __nanosleep(128);
    }
    __syncthreads();
    __threadfence();

    __shared__ int warp_sums[8];
    const int lane = tid & 31;
    const int warp = tid >> 5;
    int running = 0;
    for (int pass = 0; pass < 8; pass++) {
        int ex[4];
        #pragma unroll
        for (int j = 0; j < 4; j++)
            ex[j] = __ldcg(&g_expert[(pass * 4 + j) * 256 + tid]);
        #pragma unroll
        for (int j = 0; j < 4; j++) {
            int flag = (ex[j] == e) ? 1 : 0;
            unsigned bits = __ballot_sync(0xffffffffu, flag);
            int excl = __popc(bits & ((1u << lane) - 1u));
            if (lane == 0) warp_sums[warp] = __popc(bits);
            __syncthreads();
            int woff = 0, tot = 0;
            #pragma unroll
            for (int w = 0; w < 8; w++) {
                int ws = warp_sums[w];
                if (w < warp) woff += ws;
                tot += ws;
            }
            int pos = running + woff + excl;
            if (flag && pos < CAP) {
                int s = (pass * 4 + j) * 256 + tid;
                size_t off = (size_t)s * (E * CAP) + (size_t)e * CAP + (size_t)pos;
                outF[off] = __ldcg(&g_gate[s]);
                if (two) outF[(size_t)S * E * CAP + off] = 1.0f;
            }
            running += tot;
            __syncthreads();
        }
    }
}

// ============================================================
extern "C" void kernel_launch(void* const* d_in, const int* in_sizes, int n_in,
                              void* d_out, int out_size) {
    const float* inp = (const float*)d_in[0];   // [S, M]
    const float* wg  = (const float*)d_in[1];   // [E, M]
    float* out = (float*)d_out;

    const long long SEC = (long long)S * E * CAP;
    const int two = ((long long)out_size >= 2 * SEC) ? 1 : 0;

    const int nf4     = out_size / 4;
    const int nchunks = nf4 / CHUNK_F4;          // 4096 or 8192 (exact)
    int p1 = P1_CHUNKS;
    if (p1 > nchunks / 2) p1 = nchunks / 2;
    const int p2 = nchunks - p1;

    init_kernel<<<1, 64>>>();
    k1_kernel<<<K1_GRID, 256>>>(inp, wg, (float4*)out, p1);
    k2_kernel<<<NF2B + E, 256>>>((float4*)out, out, p1, p2, two);
}

// round 16
// speedup vs baseline: 1.1868x; 1.1868x over previous
#include <cuda_runtime.h>
#include <cstdint>

// Problem constants (fixed shapes per reference setup_inputs)
#define S 8192      // tokens
#define M 2048      // model dim
#define E 64        // experts
#define CAP 256     // capacity = TOP_K * ceil(S/E) = 2 * 128
#define KSPLIT 4
#define KCHUNK (M / KSPLIT)   // 512
#define BK 16
#define BM 128                // tokens per gemm block
#define NMB (S / BM)          // 64 token-blocks
#define NG (NMB * KSPLIT)     // 256 gemm blocks
#define NT (KCHUNK / BK)      // 32 k-tiles
#define FILL_F4_PER_BLOCK 8192
#define GF4_PER_TILE 2048               // 8 float4/thread * 256 threads
#define GF4_PER_BLOCK (GF4_PER_TILE * NT)  // 65536 f4 = 1 MB per gemm block

typedef unsigned long long ull;

// ---- device scratch (no allocations allowed; zero-initialized at load) ----
__device__ float g_part[KSPLIT][S][E];  // 8 MB partial logits (L2-resident)
__device__ int   g_expert[S];
__device__ float g_gate[S];
__device__ int   g_cnt_mb[NMB];         // per token-group gemm completion
__device__ int   g_cnt[3];              // [0]=gemm, [1]=soft, [2]=fill
__device__ int   g_rank_pass;           // rank blocks past their waits

__device__ __forceinline__ ull dup2(float x) {
    ull r; asm("mov.b64 %0, {%1, %1};" : "=l"(r) : "f"(x)); return r;
}
__device__ __forceinline__ void ffma2(ull &acc, ull a, ull b) {
    asm("fma.rn.f32x2 %0, %1, %2, %0;" : "+l"(acc) : "l"(a), "l"(b));
}
__device__ __forceinline__ float2 unpack2(ull v) {
    float2 f; asm("mov.b64 {%0, %1}, %2;" : "=f"(f.x), "=f"(f.y) : "l"(v));
    return f;
}

// Release: all block stores visible, then bump counter.
__device__ __forceinline__ void block_signal(int* c) {
    __syncthreads();
    __threadfence();
    if (threadIdx.x == 0) atomicAdd(c, 1);
}
// Acquire: spin until counter reaches target.
__device__ __forceinline__ void block_wait(int* c, int target) {
    if (threadIdx.x == 0) {
        volatile int* v = c;
        while (*v < target) __nanosleep(128);
    }
    __syncthreads();
    __threadfence();
}

// ============================================================
// Fused pipeline kernel (self-resetting; no init kernel).
// Grid layout (dispatch order):
//   [0, NG)                 : GEMM blocks (+1 MB fill rent each;
//                             ks==0 -> per-group softargmax via
//                             last-finisher handshake)
//   [NG, NG+nfill)          : pure zero-fill blocks
//   [NG+nfill, NG+nfill+E)  : rank blocks — scan EARLY (after
//                             soft), scatter after fill; block
//                             e==0 resets all counters at the end.
// ============================================================
__global__ void __launch_bounds__(256, 3) fused_kernel(const float* __restrict__ A,
                                                       const float* __restrict__ B,
                                                       float4* __restrict__ out4,
                                                       float* __restrict__ outF,
                                                       int nfill, int two) {
    const int bx  = blockIdx.x;
    const int tid = threadIdx.x;
    const float4 z = make_float4(0.f, 0.f, 0.f, 0.f);

    if (bx >= NG) {
        if (bx < NG + nfill) {
            // ---------------- pure fill branch ----------------
            const int fb = bx - NG;
            int idx = NG * GF4_PER_BLOCK + fb * FILL_F4_PER_BLOCK + tid;
            #pragma unroll 8
            for (int i = 0; i < FILL_F4_PER_BLOCK / 256; i++) {
                __stcs(&out4[idx], z);
                idx += 256;
            }
            block_signal(&g_cnt[2]);
            return;
        }
        // ---------------- rank branch ----------------
        const int e = bx - NG - nfill;
        block_wait(&g_cnt[1], NMB);   // softargmax complete -> g_expert ready

        // Early scan (overlapped with remaining fill): 2 passes of 16
        // tokens/thread; positions packed 2 x 16-bit per int.
        __shared__ int warp_sums[8];
        const int lane = tid & 31;
        const int warp = tid >> 5;
        unsigned flags = 0;
        int posp[16];
        int running = 0;
        #pragma unroll
        for (int pass = 0; pass < 2; pass++) {
            int ex[16];
            #pragma unroll
            for (int j = 0; j < 16; j++)
                ex[j] = __ldcg(&g_expert[(pass * 16 + j) * 256 + tid]);
            #pragma unroll
            for (int j = 0; j < 16; j++) {
                const int c = pass * 16 + j;
                int flag = (ex[j] == e) ? 1 : 0;
                unsigned bits = __ballot_sync(0xffffffffu, flag);
                int excl = __popc(bits & ((1u << lane) - 1u));
                if (lane == 0) warp_sums[warp] = __popc(bits);
                __syncthreads();
                int woff = 0, tot = 0;
                #pragma unroll
                for (int w = 0; w < 8; w++) {
                    int ws = warp_sums[w];
                    if (w < warp) woff += ws;
                    tot += ws;
                }
                int pos = running + woff + excl;
                flags |= ((unsigned)flag) << c;
                if (c & 1) posp[c >> 1] |= (pos & 0xffff) << 16;
                else       posp[c >> 1]  = (pos & 0xffff);
                running += tot;
                __syncthreads();
            }
        }

        block_wait(&g_cnt[2], nfill + NG);   // output fully zeroed

        // Scatter-only tail (~128 tokens per expert).
        #pragma unroll
        for (int c = 0; c < 32; c++) {
            int pos = (posp[c >> 1] >> ((c & 1) * 16)) & 0xffff;
            if (((flags >> c) & 1u) && pos < CAP) {
                int s = c * 256 + tid;
                size_t off = (size_t)s * (E * CAP) + (size_t)e * CAP + (size_t)pos;
                outF[off] = __ldcg(&g_gate[s]);
                if (two) outF[(size_t)S * E * CAP + off] = 1.0f;
            }
        }

        // Self-reset handshake: counters back to 0 for the next replay.
        block_signal(&g_rank_pass);
        if (e == 0) {
            if (tid == 0) {
                volatile int* v = &g_rank_pass;
                while (*v < E) __nanosleep(128);
            }
            __syncthreads();
            if (tid < NMB) g_cnt_mb[tid] = 0;
            if (tid == 0) {
                g_cnt[0] = 0; g_cnt[1] = 0; g_cnt[2] = 0;
                g_rank_pass = 0;
                __threadfence();
            }
        }
        return;
    }

    // ---------------- gemm branch (128x64 block tile, 8x4 thread tile) ----------------
    __shared__ __align__(16) float As[BK][BM];        // [k][token]
    __shared__ __align__(16) ull   Bs[2][BK][32];     // [plane][k][slot], dup'd {b,b}
    __shared__ int s_last;

    const int mb  = bx & (NMB - 1);   // token-block
    const int ks  = bx >> 6;          // k-split index
    const int tokBase = mb * BM;
    const int kb0 = ks * KCHUNK;

    // A loader: token = tid&127, k-quads (tid>>7) and (tid>>7)+2
    const int atok = tid & 127;
    const int akq  = tid >> 7;        // 0 or 1
    const float* arow = A + (size_t)(tokBase + atok) * M + kb0;

    // B loader: expert = tid>>2, k-quad = tid&3
    const int be = tid >> 2;
    const int bj = tid & 3;
    const float* brow = B + (size_t)be * M + kb0 + bj * 4;
    const int bp   = (be >> 1) & 1;             // plane
    const int bslt = (be >> 2) * 2 + (be & 1);  // ull slot within row

    // compute roles: 8 tokens (4 packed pairs) x 4 experts
    const int tt = tid >> 4;          // 0..15
    const int te = tid & 15;          // 0..15

    // this block's zero-fill slice (store rent): 1 MB
    float4* zp = out4 + (size_t)bx * GF4_PER_BLOCK + tid;

    ull acc[4][4];
    #pragma unroll
    for (int p = 0; p < 4; p++)
        #pragma unroll
        for (int j = 0; j < 4; j++) acc[p][j] = 0ull;

    // register-prefetch double buffering
    float4 a0 = *(const float4*)(arow + akq * 4);
    float4 a1 = *(const float4*)(arow + akq * 4 + 8);
    float4 bv = *(const float4*)(brow);

    for (int tile = 0; tile < NT; tile++) {
        __syncthreads();  // previous compute done before overwrite

        As[akq*4 + 0][atok] = a0.x;  As[akq*4 + 1][atok] = a0.y;
        As[akq*4 + 2][atok] = a0.z;  As[akq*4 + 3][atok] = a0.w;
        As[akq*4 + 8][atok] = a1.x;  As[akq*4 + 9][atok] = a1.y;
        As[akq*4 +10][atok] = a1.z;  As[akq*4 +11][atok] = a1.w;

        Bs[bp][bj*4 + 0][bslt] = dup2(bv.x);
        Bs[bp][bj*4 + 1][bslt] = dup2(bv.y);
        Bs[bp][bj*4 + 2][bslt] = dup2(bv.z);
        Bs[bp][bj*4 + 3][bslt] = dup2(bv.w);

        __syncthreads();

        if (tile + 1 < NT) {  // prefetch next tile while computing
            const int kb = (tile + 1) * BK;
            a0 = *(const float4*)(arow + kb + akq * 4);
            a1 = *(const float4*)(arow + kb + akq * 4 + 8);
            bv = *(const float4*)(brow + kb);
        }

        // zero-fill rent: 8 STG.128 per thread per tile (1 MB/block total)
        #pragma unroll
        for (int q = 0; q < 8; q++) __stcs(zp + q * 256, z);
        zp += GF4_PER_TILE;

        #pragma unroll
        for (int kk = 0; kk < BK; kk++) {
            const ulonglong2* ar = (const ulonglong2*)&As[kk][tt * 8];
            ulonglong2 a01 = ar[0];   // {t0,t1},{t2,t3}
            ulonglong2 a23 = ar[1];   // {t4,t5},{t6,t7}
            ulonglong2 b0 = ((const ulonglong2*)&Bs[0][kk][0])[te]; // e0,e1
            ulonglong2 b1 = ((const ulonglong2*)&Bs[1][kk][0])[te]; // e2,e3
            ull ap[4] = { a01.x, a01.y, a23.x, a23.y };
            #pragma unroll
            for (int p = 0; p < 4; p++) {
                ffma2(acc[p][0], ap[p], b0.x);
                ffma2(acc[p][1], ap[p], b0.y);
                ffma2(acc[p][2], ap[p], b1.x);
                ffma2(acc[p][3], ap[p], b1.y);
            }
        }
    }

    // Write partials: token rows tokBase + tt*8 + 2p (+1), experts te*4..+3
    #pragma unroll
    for (int p = 0; p < 4; p++) {
        float2 v0 = unpack2(acc[p][0]);
        float2 v1 = unpack2(acc[p][1]);
        float2 v2 = unpack2(acc[p][2]);
        float2 v3 = unpack2(acc[p][3]);
        int r0 = tokBase + tt * 8 + 2 * p;
        *(float4*)&g_part[ks][r0    ][te * 4] = make_float4(v0.x, v1.x, v2.x, v3.x);
        *(float4*)&g_part[ks][r0 + 1][te * 4] = make_float4(v0.y, v1.y, v2.y, v3.y);
    }

    // Signal gemm completion for this group; detect last finisher.
    __syncthreads();
    __threadfence();
    if (tid == 0) s_last = (atomicAdd(&g_cnt_mb[mb], 1) == KSPLIT - 1);
    block_signal(&g_cnt[2]);   // fill rent done (stores precede fence)
    __syncthreads();

    if (!s_last) return;
    __threadfence();  // acquire: other ks blocks' partials now visible

    {
        const int warp = tid >> 5;
        const int lane = tid & 31;
        #pragma unroll 2
        for (int i = 0; i < 16; i++) {
            int t = tokBase + warp * 16 + i;
            float v0 = 0.f, v1 = 0.f;
            #pragma unroll
            for (int k = 0; k < KSPLIT; k++) {
                v0 += __ldcg(&g_part[k][t][lane]);
                v1 += __ldcg(&g_part[k][t][lane + 32]);
            }
            float bvv; int bi;
            if (v0 >= v1) { bvv = v0; bi = lane; }
            else          { bvv = v1; bi = lane + 32; }
            #pragma unroll
            for (int off = 16; off; off >>= 1) {
                float ov = __shfl_xor_sync(0xffffffffu, bvv, off);
                int   oi = __shfl_xor_sync(0xffffffffu, bi, off);
                if (ov > bvv || (ov == bvv && oi < bi)) { bvv = ov; bi = oi; }
            }
            float ssum = expf(v0 - bvv) + expf(v1 - bvv);
            #pragma unroll
            for (int off = 16; off; off >>= 1)
                ssum += __shfl_xor_sync(0xffffffffu, ssum, off);
            if (lane == 0) {
                g_expert[t] = bi;
                g_gate[t]   = 1.0f / ssum;
            }
        }
    }
    block_signal(&g_cnt[1]);
}

// ============================================================
extern "C" void kernel_launch(void* const* d_in, const int* in_sizes, int n_in,
                              void* d_out, int out_size) {
    const float* inp = (const float*)d_in[0];   // [S, M]
    const float* wg  = (const float*)d_in[1];   // [E, M]
    float* out = (float*)d_out;

    const long long SEC = (long long)S * E * CAP;
    const int two = ((long long)out_size >= 2 * SEC) ? 1 : 0;

    const int nf4      = out_size / 4;
    const int nf4_rest = nf4 - NG * GF4_PER_BLOCK;          // exact fit
    const int nfill    = nf4_rest / FILL_F4_PER_BLOCK;      // divides exactly

    fused_kernel<<<NG + nfill + E, 256>>>(inp, wg, (float4*)out, out, nfill, two);
}